// round 8
// baseline (speedup 1.0000x reference)
#include <cuda_runtime.h>
#include <cuda_fp16.h>
#include <cstdint>

#define NN 4096
#define DD 512
#define BM 128
#define BN 128
#define KC 64                    // fp16 K elems per chunk = 128B per row
#define NCHUNK (DD / KC)         // 8
#define NSTAGE 3
#define NTILES ((NN / BM) * (NN / BN))   // 1024
#define MARGIN_F 0.3f

#define STAGE_BYTES (2 * BM * 128)       // A(16KB)+B(16KB) = 32 KB per stage
#define A_OFF(s) ((s) * STAGE_BYTES)
#define B_OFF(s) ((s) * STAGE_BYTES + BM * 128)
#define DYN_SMEM (NSTAGE * STAGE_BYTES)  // 96 KB

__device__ float    g_e1[NN];
__device__ float    g_e2[NN];
__device__ unsigned g_ap[NN];      // non-negative float bits, atomicMax
__device__ unsigned g_an[NN];      // non-negative float bits, atomicMin
__device__ int      g_lab[NN];
__device__ __half   g_srch[NN * DD];   // fp16 copies (4 MB each)
__device__ __half   g_tgth[NN * DD];
__device__ unsigned g_done;

// ---------------------------------------------------------------------------
__device__ __forceinline__ uint32_t h2_bits(__half2 h) {
    return *reinterpret_cast<uint32_t*>(&h);
}
__device__ __forceinline__ uint32_t smem_u32(const void* p) {
    uint32_t a;
    asm("{ .reg .u64 t; cvta.to.shared.u64 t, %1; cvt.u32.u64 %0, t; }"
        : "=r"(a) : "l"(p));
    return a;
}
__device__ __forceinline__ void cp_async16(uint32_t dst, const void* src) {
    asm volatile("cp.async.cg.shared.global [%0], [%1], 16;" :: "r"(dst), "l"(src));
}
__device__ __forceinline__ void ldsm_x4(uint32_t addr, uint32_t& r0, uint32_t& r1,
                                        uint32_t& r2, uint32_t& r3) {
    asm volatile("ldmatrix.sync.aligned.m8n8.x4.shared.b16 {%0,%1,%2,%3}, [%4];"
                 : "=r"(r0), "=r"(r1), "=r"(r2), "=r"(r3) : "r"(addr));
}
__device__ __forceinline__ void mma_f16(float* d, uint32_t a0, uint32_t a1,
                                        uint32_t a2, uint32_t a3,
                                        uint32_t b0, uint32_t b1) {
    asm volatile(
        "mma.sync.aligned.m16n8k16.row.col.f32.f16.f16.f32 "
        "{%0,%1,%2,%3}, {%4,%5,%6,%7}, {%8,%9}, {%0,%1,%2,%3};"
        : "+f"(d[0]), "+f"(d[1]), "+f"(d[2]), "+f"(d[3])
        : "r"(a0), "r"(a1), "r"(a2), "r"(a3), "r"(b0), "r"(b1));
}

// ---------------------------------------------------------------------------
// prep: fp32->fp16 convert + per-row squared norms + accumulator init.
// Block 0 additionally: label dtype detect + normalize, done-counter reset.
// ---------------------------------------------------------------------------
__global__ void prep_kernel(const float* __restrict__ src,
                            const float* __restrict__ tgt,
                            const int* __restrict__ lab32) {
    int row = blockIdx.x;
    int t = threadIdx.x;  // 128
    const float4* s4 = (const float4*)(src + (size_t)row * DD);
    const float4* g4 = (const float4*)(tgt + (size_t)row * DD);
    uint2* sh = (uint2*)(g_srch + (size_t)row * DD);
    uint2* gh = (uint2*)(g_tgth + (size_t)row * DD);
    float a = 0.f, b = 0.f;
    {
        float4 x = s4[t];
        a = x.x*x.x + x.y*x.y + x.z*x.z + x.w*x.w;
        uint2 o;
        o.x = h2_bits(__floats2half2_rn(x.x, x.y));
        o.y = h2_bits(__floats2half2_rn(x.z, x.w));
        sh[t] = o;
        float4 y = g4[t];
        b = y.x*y.x + y.y*y.y + y.z*y.z + y.w*y.w;
        o.x = h2_bits(__floats2half2_rn(y.x, y.y));
        o.y = h2_bits(__floats2half2_rn(y.z, y.w));
        gh[t] = o;
    }
#pragma unroll
    for (int o = 16; o > 0; o >>= 1) {
        a += __shfl_xor_sync(0xffffffffu, a, o);
        b += __shfl_xor_sync(0xffffffffu, b, o);
    }
    __shared__ float sa[4], sb[4];
    int w = t >> 5;
    if ((t & 31) == 0) { sa[w] = a; sb[w] = b; }
    __syncthreads();
    if (t == 0) {
        g_e1[row] = sa[0] + sa[1] + sa[2] + sa[3];
        g_e2[row] = sb[0] + sb[1] + sb[2] + sb[3];
        g_ap[row] = 0u;
        g_an[row] = 0x7f800000u;
    }

    // ---- block 0 extra duty: labels + counter ----
    if (row == 0) {
        __shared__ int any_odd_nonzero;
        if (t == 0) { any_odd_nonzero = 0; g_done = 0u; }
        __syncthreads();
        int local = 0;
        for (int i = 2 * t + 1; i < NN; i += 2 * 128)
            if (lab32[i] != 0) local = 1;
        if (local) atomicOr(&any_odd_nonzero, 1);
        __syncthreads();
        bool is64 = (any_odd_nonzero == 0);
        for (int i = t; i < NN; i += 128)
            g_lab[i] = is64 ? lab32[2 * i] : lab32[i];
    }
}

// ---------------------------------------------------------------------------
// dist_mma: 128x128 tile via mma.sync fp16 m16n8k16, ldmatrix fragment feed,
// 3-stage cp.async pipeline, fused label-masked row max/min epilogue,
// last-CTA-out performs the final mean reduction into d_out.
// 8 warps: 4 (M) x 2 (N); warp tile 32x64.
// ---------------------------------------------------------------------------
__global__ void __launch_bounds__(256, 2) dist_mma_kernel(float* __restrict__ out) {
    extern __shared__ char smem[];
    __shared__ float sE1[BM], sE2[BN];
    __shared__ int   sLr[BM], sLc[BN];
    __shared__ unsigned sAp[BM], sAn[BM];
    __shared__ int s_winner;
    __shared__ float s_red[32];

    const int tid = threadIdx.x;
    const int wid = tid >> 5;
    const int lid = tid & 31;
    const int gid = lid >> 2;
    const int t4  = lid & 3;
    const int warpM = wid & 3;
    const int warpN = wid >> 2;
    const int rowBase = blockIdx.y * BM;
    const int colBase = blockIdx.x * BN;

    if (tid < 128) {
        sAp[tid] = 0u;
        sAn[tid] = 0x7f800000u;
        sE1[tid] = g_e1[rowBase + tid];
        sE2[tid] = g_e2[colBase + tid];
        sLr[tid] = g_lab[rowBase + tid];
        sLc[tid] = g_lab[colBase + tid];
    }

    const uint32_t sbase = smem_u32(smem);
    const int l7 = lid & 7;
    uint32_t aRow[2];
#pragma unroll
    for (int mf = 0; mf < 2; mf++)
        aRow[mf] = (uint32_t)((warpM * 32 + mf * 16 + ((lid >> 3) & 1) * 8 + l7) * 128);
    const int aSel = lid >> 4;
    uint32_t bCol[4];
#pragma unroll
    for (int p = 0; p < 4; p++)
        bCol[p] = (uint32_t)((warpN * 64 + p * 16 + (lid >> 4) * 8 + l7) * 128);
    const int bSel = (lid >> 3) & 1;

    // chunk loader: 128 rows x 128B (= 64 fp16), SW128 swizzle
    auto load_chunk = [&](const __half* __restrict__ base, int rb, int kt, uint32_t dst) {
#pragma unroll
        for (int i = 0; i < 4; i++) {
            int f = tid + i * 256;
            int r = f >> 3;
            int c16 = f & 7;
            const __half* g = base + (size_t)(rb + r) * DD + kt + c16 * 8;
            cp_async16(dst + r * 128 + ((c16 ^ (r & 7)) << 4), g);
        }
    };

    float acc[2][8][4];
#pragma unroll
    for (int mf = 0; mf < 2; mf++)
#pragma unroll
        for (int nf = 0; nf < 8; nf++)
#pragma unroll
            for (int v = 0; v < 4; v++) acc[mf][nf][v] = 0.f;

    load_chunk(g_srch, rowBase, 0, sbase + A_OFF(0));
    load_chunk(g_tgth, colBase, 0, sbase + B_OFF(0));
    asm volatile("cp.async.commit_group;");
    load_chunk(g_srch, rowBase, KC, sbase + A_OFF(1));
    load_chunk(g_tgth, colBase, KC, sbase + B_OFF(1));
    asm volatile("cp.async.commit_group;");

    for (int c = 0; c < NCHUNK; c++) {
        int st = c % NSTAGE;
        if (c + 2 < NCHUNK) {
            int sn = (c + 2) % NSTAGE;
            load_chunk(g_srch, rowBase, (c + 2) * KC, sbase + A_OFF(sn));
            load_chunk(g_tgth, colBase, (c + 2) * KC, sbase + B_OFF(sn));
            asm volatile("cp.async.commit_group;");
            asm volatile("cp.async.wait_group 2;");
        } else if (c + 1 < NCHUNK) {
            asm volatile("cp.async.wait_group 1;");
        } else {
            asm volatile("cp.async.wait_group 0;");
        }
        __syncthreads();

        const uint32_t Ab = sbase + A_OFF(st);
        const uint32_t Bb = sbase + B_OFF(st);
#pragma unroll
        for (int s = 0; s < 4; s++) {          // 4 x K=16
            uint32_t a[2][4];
#pragma unroll
            for (int mf = 0; mf < 2; mf++) {
                uint32_t addr = Ab + aRow[mf] + ((uint32_t)((s * 2 + aSel) ^ l7) << 4);
                ldsm_x4(addr, a[mf][0], a[mf][1], a[mf][2], a[mf][3]);
            }
#pragma unroll
            for (int p = 0; p < 4; p++) {
                uint32_t b0a, b1a, b0b, b1b;
                uint32_t addr = Bb + bCol[p] + ((uint32_t)((s * 2 + bSel) ^ l7) << 4);
                ldsm_x4(addr, b0a, b1a, b0b, b1b);
                mma_f16(acc[0][2 * p],     a[0][0], a[0][1], a[0][2], a[0][3], b0a, b1a);
                mma_f16(acc[1][2 * p],     a[1][0], a[1][1], a[1][2], a[1][3], b0a, b1a);
                mma_f16(acc[0][2 * p + 1], a[0][0], a[0][1], a[0][2], a[0][3], b0b, b1b);
                mma_f16(acc[1][2 * p + 1], a[1][0], a[1][1], a[1][2], a[1][3], b0b, b1b);
            }
        }
        __syncthreads();
    }

    // ---- epilogue: dist -> clamp -> mask -> row max/min ----
#pragma unroll
    for (int mf = 0; mf < 2; mf++) {
#pragma unroll
        for (int half = 0; half < 2; half++) {
            int row = warpM * 32 + mf * 16 + half * 8 + gid;
            float e1v = sE1[row];
            int   lr  = sLr[row];
            float apv = 0.f;
            float anv = __int_as_float(0x7f800000);
#pragma unroll
            for (int nf = 0; nf < 8; nf++) {
                int c0 = warpN * 64 + nf * 8 + t4 * 2;
#pragma unroll
                for (int v = 0; v < 2; v++) {
                    int col = c0 + v;
                    float d = fmaf(-2.f, acc[mf][nf][half * 2 + v], e1v + sE2[col]);
                    d = fmaxf(d, 0.f);
                    if (lr == sLc[col]) apv = fmaxf(apv, d);
                    else                anv = fminf(anv, d);
                }
            }
#pragma unroll
            for (int o = 1; o <= 2; o <<= 1) {
                apv = fmaxf(apv, __shfl_xor_sync(0xffffffffu, apv, o));
                anv = fminf(anv, __shfl_xor_sync(0xffffffffu, anv, o));
            }
            if (t4 == 0) {
                atomicMax(&sAp[row], __float_as_uint(apv));
                atomicMin(&sAn[row], __float_as_uint(anv));
            }
        }
    }
    __syncthreads();
    if (tid < 128) {
        atomicMax(&g_ap[rowBase + tid], sAp[tid]);
        atomicMin(&g_an[rowBase + tid], sAn[tid]);
    }
    __syncthreads();

    // ---- last CTA out performs the final reduction ----
    if (tid == 0) {
        __threadfence();
        unsigned old = atomicAdd(&g_done, 1u);
        s_winner = (old == NTILES - 1) ? 1 : 0;
    }
    __syncthreads();
    if (s_winner) {
        float s = 0.f;
        for (int i = tid * 4; i < NN; i += 256 * 4) {
            uint4 ap4 = __ldcg((const uint4*)&g_ap[i]);
            uint4 an4 = __ldcg((const uint4*)&g_an[i]);
            s += fmaxf(__uint_as_float(ap4.x) - __uint_as_float(an4.x) + MARGIN_F, 0.f);
            s += fmaxf(__uint_as_float(ap4.y) - __uint_as_float(an4.y) + MARGIN_F, 0.f);
            s += fmaxf(__uint_as_float(ap4.z) - __uint_as_float(an4.z) + MARGIN_F, 0.f);
            s += fmaxf(__uint_as_float(ap4.w) - __uint_as_float(an4.w) + MARGIN_F, 0.f);
        }
#pragma unroll
        for (int o = 16; o > 0; o >>= 1) s += __shfl_xor_sync(0xffffffffu, s, o);
        if (lid == 0) s_red[wid] = s;
        __syncthreads();
        if (tid < 8) {
            float v = s_red[tid];
#pragma unroll
            for (int o = 4; o > 0; o >>= 1) v += __shfl_xor_sync(0xffu, v, o);
            if (tid == 0) out[0] = v * (1.0f / (float)NN);
        }
    }
}

// ---------------------------------------------------------------------------
extern "C" void kernel_launch(void* const* d_in, const int* in_sizes, int n_in,
                              void* d_out, int out_size) {
    const float* src = (const float*)d_in[0];
    const float* tgt = (const float*)d_in[1];
    const int*   lab = (const int*)d_in[2];

    cudaFuncSetAttribute(dist_mma_kernel,
                         cudaFuncAttributeMaxDynamicSharedMemorySize, DYN_SMEM);

    prep_kernel<<<NN, 128>>>(src, tgt, lab);
    dist_mma_kernel<<<dim3(NN / BN, NN / BM), 256, DYN_SMEM>>>((float*)d_out);
}

// round 9
// speedup vs baseline: 1.2186x; 1.2186x over previous
#include <cuda_runtime.h>
#include <cuda_fp16.h>
#include <cstdint>

#define NN 4096
#define DD 512
#define BM 128
#define BN 128
#define KC 64                    // fp16 K elems per chunk = 128B per row
#define NCHUNK (DD / KC)         // 8
#define NSTAGE 3
#define MARGIN_F 0.3f

#define STAGE_BYTES (2 * BM * 128)       // A(16KB)+B(16KB) per stage
#define A_OFF(s) ((s) * STAGE_BYTES)
#define B_OFF(s) ((s) * STAGE_BYTES + BM * 128)
#define DYN_SMEM (NSTAGE * STAGE_BYTES)  // 96 KB

__device__ float    g_e1[NN];
__device__ float    g_e2[NN];
__device__ unsigned g_ap[NN];      // non-negative float bits, atomicMax
__device__ unsigned g_an[NN];      // non-negative float bits, atomicMin
__device__ int      g_lab[NN];
__device__ __half   g_srch[NN * DD];   // fp16 copies (4 MB each)
__device__ __half   g_tgth[NN * DD];

// ---------------------------------------------------------------------------
__device__ __forceinline__ uint32_t h2_bits(__half2 h) {
    return *reinterpret_cast<uint32_t*>(&h);
}
__device__ __forceinline__ uint32_t smem_u32(const void* p) {
    uint32_t a;
    asm("{ .reg .u64 t; cvta.to.shared.u64 t, %1; cvt.u32.u64 %0, t; }"
        : "=r"(a) : "l"(p));
    return a;
}
__device__ __forceinline__ void cp_async16(uint32_t dst, const void* src) {
    asm volatile("cp.async.cg.shared.global [%0], [%1], 16;" :: "r"(dst), "l"(src));
}
__device__ __forceinline__ void ldsm_x4(uint32_t addr, uint32_t& r0, uint32_t& r1,
                                        uint32_t& r2, uint32_t& r3) {
    asm volatile("ldmatrix.sync.aligned.m8n8.x4.shared.b16 {%0,%1,%2,%3}, [%4];"
                 : "=r"(r0), "=r"(r1), "=r"(r2), "=r"(r3) : "r"(addr));
}
__device__ __forceinline__ void mma_f16(float* d, uint32_t a0, uint32_t a1,
                                        uint32_t a2, uint32_t a3,
                                        uint32_t b0, uint32_t b1) {
    asm volatile(
        "mma.sync.aligned.m16n8k16.row.col.f32.f16.f16.f32 "
        "{%0,%1,%2,%3}, {%4,%5,%6,%7}, {%8,%9}, {%0,%1,%2,%3};"
        : "+f"(d[0]), "+f"(d[1]), "+f"(d[2]), "+f"(d[3])
        : "r"(a0), "r"(a1), "r"(a2), "r"(a3), "r"(b0), "r"(b1));
}

// ---------------------------------------------------------------------------
// prep: fp32->fp16 convert + per-row squared norms + accumulator init.
// Block 0 additionally: label dtype detect + normalize.
// ---------------------------------------------------------------------------
__global__ void prep_kernel(const float* __restrict__ src,
                            const float* __restrict__ tgt,
                            const int* __restrict__ lab32) {
    int row = blockIdx.x;
    int t = threadIdx.x;  // 128
    const float4* s4 = (const float4*)(src + (size_t)row * DD);
    const float4* g4 = (const float4*)(tgt + (size_t)row * DD);
    uint2* sh = (uint2*)(g_srch + (size_t)row * DD);
    uint2* gh = (uint2*)(g_tgth + (size_t)row * DD);
    float a = 0.f, b = 0.f;
    {
        float4 x = s4[t];
        a = x.x*x.x + x.y*x.y + x.z*x.z + x.w*x.w;
        uint2 o;
        o.x = h2_bits(__floats2half2_rn(x.x, x.y));
        o.y = h2_bits(__floats2half2_rn(x.z, x.w));
        sh[t] = o;
        float4 y = g4[t];
        b = y.x*y.x + y.y*y.y + y.z*y.z + y.w*y.w;
        o.x = h2_bits(__floats2half2_rn(y.x, y.y));
        o.y = h2_bits(__floats2half2_rn(y.z, y.w));
        gh[t] = o;
    }
#pragma unroll
    for (int o = 16; o > 0; o >>= 1) {
        a += __shfl_xor_sync(0xffffffffu, a, o);
        b += __shfl_xor_sync(0xffffffffu, b, o);
    }
    __shared__ float sa[4], sb[4];
    int w = t >> 5;
    if ((t & 31) == 0) { sa[w] = a; sb[w] = b; }
    __syncthreads();
    if (t == 0) {
        g_e1[row] = sa[0] + sa[1] + sa[2] + sa[3];
        g_e2[row] = sb[0] + sb[1] + sb[2] + sb[3];
        g_ap[row] = 0u;
        g_an[row] = 0x7f800000u;
    }

    // ---- block 0 extra duty: labels ----
    if (row == 0) {
        __shared__ int any_odd_nonzero;
        if (t == 0) any_odd_nonzero = 0;
        __syncthreads();
        int local = 0;
        for (int i = 2 * t + 1; i < NN; i += 2 * 128)
            if (lab32[i] != 0) local = 1;
        if (local) atomicOr(&any_odd_nonzero, 1);
        __syncthreads();
        bool is64 = (any_odd_nonzero == 0);
        for (int i = t; i < NN; i += 128)
            g_lab[i] = is64 ? lab32[2 * i] : lab32[i];
    }
}

// ---------------------------------------------------------------------------
// dist_mma: 128x128 tile via mma.sync fp16 m16n8k16, ldmatrix fragment feed,
// 3-stage cp.async pipeline with ONE barrier per chunk (CUTLASS multistage
// pattern), fused label-masked row max/min epilogue.
// 8 warps: 4 (M) x 2 (N); warp tile 32x64.
// ---------------------------------------------------------------------------
__global__ void __launch_bounds__(256, 2) dist_mma_kernel() {
    extern __shared__ char smem[];
    __shared__ float sE1[BM], sE2[BN];
    __shared__ int   sLr[BM], sLc[BN];
    __shared__ unsigned sAp[BM], sAn[BM];

    const int tid = threadIdx.x;
    const int wid = tid >> 5;
    const int lid = tid & 31;
    const int gid = lid >> 2;
    const int t4  = lid & 3;
    const int warpM = wid & 3;
    const int warpN = wid >> 2;
    const int rowBase = blockIdx.y * BM;
    const int colBase = blockIdx.x * BN;

    if (tid < 128) {
        sAp[tid] = 0u;
        sAn[tid] = 0x7f800000u;
        sE1[tid] = g_e1[rowBase + tid];
        sE2[tid] = g_e2[colBase + tid];
        sLr[tid] = g_lab[rowBase + tid];
        sLc[tid] = g_lab[colBase + tid];
    }

    const uint32_t sbase = smem_u32(smem);
    const int l7 = lid & 7;
    uint32_t aRow[2];
#pragma unroll
    for (int mf = 0; mf < 2; mf++)
        aRow[mf] = (uint32_t)((warpM * 32 + mf * 16 + ((lid >> 3) & 1) * 8 + l7) * 128);
    const int aSel = lid >> 4;
    uint32_t bCol[4];
#pragma unroll
    for (int p = 0; p < 4; p++)
        bCol[p] = (uint32_t)((warpN * 64 + p * 16 + (lid >> 4) * 8 + l7) * 128);
    const int bSel = (lid >> 3) & 1;

    // chunk loader: 128 rows x 128B (= 64 fp16), SW128 swizzle
    auto load_chunk = [&](const __half* __restrict__ base, int rb, int kt, uint32_t dst) {
#pragma unroll
        for (int i = 0; i < 4; i++) {
            int f = tid + i * 256;
            int r = f >> 3;
            int c16 = f & 7;
            const __half* g = base + (size_t)(rb + r) * DD + kt + c16 * 8;
            cp_async16(dst + r * 128 + ((c16 ^ (r & 7)) << 4), g);
        }
    };

    float acc[2][8][4];
#pragma unroll
    for (int mf = 0; mf < 2; mf++)
#pragma unroll
        for (int nf = 0; nf < 8; nf++)
#pragma unroll
            for (int v = 0; v < 4; v++) acc[mf][nf][v] = 0.f;

    // prologue: chunks 0,1 in flight
    load_chunk(g_srch, rowBase, 0, sbase + A_OFF(0));
    load_chunk(g_tgth, colBase, 0, sbase + B_OFF(0));
    asm volatile("cp.async.commit_group;");
    load_chunk(g_srch, rowBase, KC, sbase + A_OFF(1));
    load_chunk(g_tgth, colBase, KC, sbase + B_OFF(1));
    asm volatile("cp.async.commit_group;");

    for (int c = 0; c < NCHUNK; c++) {
        // ensure chunk c's fills landed (chunk c+1 may stay in flight)
        if (c + 1 < NCHUNK) asm volatile("cp.async.wait_group 1;");
        else                asm volatile("cp.async.wait_group 0;");
        // single barrier: (1) publish chunk c fills to all threads,
        // (2) all warps finished computing chunk c-1 -> its stage is reusable
        __syncthreads();
        if (c + 2 < NCHUNK) {
            int sn = (c + 2) % NSTAGE;   // == (c-1)%NSTAGE, consumed at c-1
            load_chunk(g_srch, rowBase, (c + 2) * KC, sbase + A_OFF(sn));
            load_chunk(g_tgth, colBase, (c + 2) * KC, sbase + B_OFF(sn));
            asm volatile("cp.async.commit_group;");
        }

        const uint32_t Ab = sbase + A_OFF(c % NSTAGE);
        const uint32_t Bb = sbase + B_OFF(c % NSTAGE);
#pragma unroll
        for (int s = 0; s < 4; s++) {          // 4 x K=16
            uint32_t a[2][4];
#pragma unroll
            for (int mf = 0; mf < 2; mf++) {
                uint32_t addr = Ab + aRow[mf] + ((uint32_t)((s * 2 + aSel) ^ l7) << 4);
                ldsm_x4(addr, a[mf][0], a[mf][1], a[mf][2], a[mf][3]);
            }
#pragma unroll
            for (int p = 0; p < 4; p++) {
                uint32_t b0a, b1a, b0b, b1b;
                uint32_t addr = Bb + bCol[p] + ((uint32_t)((s * 2 + bSel) ^ l7) << 4);
                ldsm_x4(addr, b0a, b1a, b0b, b1b);
                mma_f16(acc[0][2 * p],     a[0][0], a[0][1], a[0][2], a[0][3], b0a, b1a);
                mma_f16(acc[1][2 * p],     a[1][0], a[1][1], a[1][2], a[1][3], b0a, b1a);
                mma_f16(acc[0][2 * p + 1], a[0][0], a[0][1], a[0][2], a[0][3], b0b, b1b);
                mma_f16(acc[1][2 * p + 1], a[1][0], a[1][1], a[1][2], a[1][3], b0b, b1b);
            }
        }
    }
    __syncthreads();   // protect sAp/sAn init vs epilogue (and last stage)

    // ---- epilogue: dist -> clamp -> mask -> row max/min ----
#pragma unroll
    for (int mf = 0; mf < 2; mf++) {
#pragma unroll
        for (int half = 0; half < 2; half++) {
            int row = warpM * 32 + mf * 16 + half * 8 + gid;
            float e1v = sE1[row];
            int   lr  = sLr[row];
            float apv = 0.f;
            float anv = __int_as_float(0x7f800000);
#pragma unroll
            for (int nf = 0; nf < 8; nf++) {
                int c0 = warpN * 64 + nf * 8 + t4 * 2;
#pragma unroll
                for (int v = 0; v < 2; v++) {
                    int col = c0 + v;
                    float d = fmaf(-2.f, acc[mf][nf][half * 2 + v], e1v + sE2[col]);
                    d = fmaxf(d, 0.f);
                    if (lr == sLc[col]) apv = fmaxf(apv, d);
                    else                anv = fminf(anv, d);
                }
            }
#pragma unroll
            for (int o = 1; o <= 2; o <<= 1) {
                apv = fmaxf(apv, __shfl_xor_sync(0xffffffffu, apv, o));
                anv = fminf(anv, __shfl_xor_sync(0xffffffffu, anv, o));
            }
            if (t4 == 0) {
                atomicMax(&sAp[row], __float_as_uint(apv));
                atomicMin(&sAn[row], __float_as_uint(anv));
            }
        }
    }
    __syncthreads();
    if (tid < 128) {
        atomicMax(&g_ap[rowBase + tid], sAp[tid]);
        atomicMin(&g_an[rowBase + tid], sAn[tid]);
    }
}

// ---------------------------------------------------------------------------
// reduce: deterministic single-block mean of relu(ap - an + margin)
// ---------------------------------------------------------------------------
__global__ void reduce_kernel(float* __restrict__ out) {
    __shared__ float sw[32];
    int t = threadIdx.x;  // 1024
    float s = 0.f;
#pragma unroll
    for (int i = t; i < NN; i += 1024) {
        float ap = __uint_as_float(g_ap[i]);
        float an = __uint_as_float(g_an[i]);
        s += fmaxf(ap - an + MARGIN_F, 0.f);
    }
#pragma unroll
    for (int o = 16; o > 0; o >>= 1) s += __shfl_xor_sync(0xffffffffu, s, o);
    if ((t & 31) == 0) sw[t >> 5] = s;
    __syncthreads();
    if (t < 32) {
        float v = sw[t];
#pragma unroll
        for (int o = 16; o > 0; o >>= 1) v += __shfl_xor_sync(0xffffffffu, v, o);
        if (t == 0) out[0] = v * (1.0f / (float)NN);
    }
}

// ---------------------------------------------------------------------------
extern "C" void kernel_launch(void* const* d_in, const int* in_sizes, int n_in,
                              void* d_out, int out_size) {
    const float* src = (const float*)d_in[0];
    const float* tgt = (const float*)d_in[1];
    const int*   lab = (const int*)d_in[2];

    cudaFuncSetAttribute(dist_mma_kernel,
                         cudaFuncAttributeMaxDynamicSharedMemorySize, DYN_SMEM);

    prep_kernel<<<NN, 128>>>(src, tgt, lab);
    dist_mma_kernel<<<dim3(NN / BN, NN / BM), 256, DYN_SMEM>>>();
    reduce_kernel<<<1, 1024>>>((float*)d_out);
}

// round 10
// speedup vs baseline: 1.2242x; 1.0046x over previous
#include <cuda_runtime.h>
#include <cuda_fp16.h>
#include <cstdint>

#define NN 4096
#define DD 512
#define BM 128
#define BN 128
#define KC 64                    // fp16 K elems per chunk = 128B per row
#define NCHUNK (DD / KC)         // 8
#define NSTAGE 3
#define MARGIN_F 0.3f

#define STAGE_BYTES (2 * BM * 128)       // A(16KB)+B(16KB) per stage
#define A_OFF(s) ((s) * STAGE_BYTES)
#define B_OFF(s) ((s) * STAGE_BYTES + BM * 128)
#define DYN_SMEM (NSTAGE * STAGE_BYTES)  // 96 KB

__device__ float    g_e1[NN];
__device__ float    g_e2[NN];
__device__ unsigned g_ap[NN];      // non-negative float bits, atomicMax
__device__ unsigned g_an[NN];      // non-negative float bits, atomicMin
__device__ int      g_lab[NN];
__device__ __half   g_srch[NN * DD];   // fp16 copies (4 MB each)
__device__ __half   g_tgth[NN * DD];

// ---------------------------------------------------------------------------
__device__ __forceinline__ uint32_t h2_bits(__half2 h) {
    return *reinterpret_cast<uint32_t*>(&h);
}
__device__ __forceinline__ uint32_t smem_u32(const void* p) {
    uint32_t a;
    asm("{ .reg .u64 t; cvta.to.shared.u64 t, %1; cvt.u32.u64 %0, t; }"
        : "=r"(a) : "l"(p));
    return a;
}
__device__ __forceinline__ void cp_async16(uint32_t dst, const void* src) {
    asm volatile("cp.async.cg.shared.global [%0], [%1], 16;" :: "r"(dst), "l"(src));
}
__device__ __forceinline__ void ldsm_x4(uint32_t addr, uint32_t& r0, uint32_t& r1,
                                        uint32_t& r2, uint32_t& r3) {
    asm volatile("ldmatrix.sync.aligned.m8n8.x4.shared.b16 {%0,%1,%2,%3}, [%4];"
                 : "=r"(r0), "=r"(r1), "=r"(r2), "=r"(r3) : "r"(addr));
}
__device__ __forceinline__ void mma_f16(float* d, uint32_t a0, uint32_t a1,
                                        uint32_t a2, uint32_t a3,
                                        uint32_t b0, uint32_t b1) {
    asm volatile(
        "mma.sync.aligned.m16n8k16.row.col.f32.f16.f16.f32 "
        "{%0,%1,%2,%3}, {%4,%5,%6,%7}, {%8,%9}, {%0,%1,%2,%3};"
        : "+f"(d[0]), "+f"(d[1]), "+f"(d[2]), "+f"(d[3])
        : "r"(a0), "r"(a1), "r"(a2), "r"(a3), "r"(b0), "r"(b1));
}

// ---------------------------------------------------------------------------
// prep: warp-per-row fp32->fp16 convert + squared norms + accumulator init.
// 512 blocks x 256 threads (8 warps = 8 rows/block). Each lane holds 8
// independent LDG.128 in flight (4 src + 4 tgt). Warp-shuffle reduction only.
// Block 0 additionally: label dtype detect + normalize.
// ---------------------------------------------------------------------------
__global__ void __launch_bounds__(256) prep_kernel(const float* __restrict__ src,
                                                   const float* __restrict__ tgt,
                                                   const int* __restrict__ lab32) {
    const int wid = threadIdx.x >> 5;
    const int lid = threadIdx.x & 31;
    const int row = blockIdx.x * 8 + wid;

    const float4* s4 = (const float4*)(src + (size_t)row * DD);
    const float4* g4 = (const float4*)(tgt + (size_t)row * DD);
    uint2* sh = (uint2*)(g_srch + (size_t)row * DD);
    uint2* gh = (uint2*)(g_tgth + (size_t)row * DD);

    float4 xs[4], ys[4];
#pragma unroll
    for (int i = 0; i < 4; i++) xs[i] = s4[lid + 32 * i];
#pragma unroll
    for (int i = 0; i < 4; i++) ys[i] = g4[lid + 32 * i];

    float a = 0.f, b = 0.f;
#pragma unroll
    for (int i = 0; i < 4; i++) {
        float4 x = xs[i];
        a = fmaf(x.x, x.x, a); a = fmaf(x.y, x.y, a);
        a = fmaf(x.z, x.z, a); a = fmaf(x.w, x.w, a);
        uint2 o;
        o.x = h2_bits(__floats2half2_rn(x.x, x.y));
        o.y = h2_bits(__floats2half2_rn(x.z, x.w));
        sh[lid + 32 * i] = o;
        float4 y = ys[i];
        b = fmaf(y.x, y.x, b); b = fmaf(y.y, y.y, b);
        b = fmaf(y.z, y.z, b); b = fmaf(y.w, y.w, b);
        o.x = h2_bits(__floats2half2_rn(y.x, y.y));
        o.y = h2_bits(__floats2half2_rn(y.z, y.w));
        gh[lid + 32 * i] = o;
    }
#pragma unroll
    for (int o = 16; o > 0; o >>= 1) {
        a += __shfl_xor_sync(0xffffffffu, a, o);
        b += __shfl_xor_sync(0xffffffffu, b, o);
    }
    if (lid == 0) {
        g_e1[row] = a;
        g_e2[row] = b;
        g_ap[row] = 0u;
        g_an[row] = 0x7f800000u;
    }

    // ---- block 0 extra duty: labels (global dtype detection) ----
    if (blockIdx.x == 0) {
        __shared__ int any_odd_nonzero;
        const int t = threadIdx.x;
        if (t == 0) any_odd_nonzero = 0;
        __syncthreads();
        int local = 0;
        for (int i = 2 * t + 1; i < NN; i += 2 * 256)
            if (lab32[i] != 0) local = 1;
        if (local) atomicOr(&any_odd_nonzero, 1);
        __syncthreads();
        bool is64 = (any_odd_nonzero == 0);
        for (int i = t; i < NN; i += 256)
            g_lab[i] = is64 ? lab32[2 * i] : lab32[i];
    }
}

// ---------------------------------------------------------------------------
// dist_mma: 128x128 tile via mma.sync fp16 m16n8k16, ldmatrix fragment feed,
// 3-stage cp.async pipeline with ONE barrier per chunk (CUTLASS multistage
// pattern), fused label-masked row max/min epilogue.
// 8 warps: 4 (M) x 2 (N); warp tile 32x64.
// ---------------------------------------------------------------------------
__global__ void __launch_bounds__(256, 2) dist_mma_kernel() {
    extern __shared__ char smem[];
    __shared__ float sE1[BM], sE2[BN];
    __shared__ int   sLr[BM], sLc[BN];
    __shared__ unsigned sAp[BM], sAn[BM];

    const int tid = threadIdx.x;
    const int wid = tid >> 5;
    const int lid = tid & 31;
    const int gid = lid >> 2;
    const int t4  = lid & 3;
    const int warpM = wid & 3;
    const int warpN = wid >> 2;
    const int rowBase = blockIdx.y * BM;
    const int colBase = blockIdx.x * BN;

    if (tid < 128) {
        sAp[tid] = 0u;
        sAn[tid] = 0x7f800000u;
        sE1[tid] = g_e1[rowBase + tid];
        sE2[tid] = g_e2[colBase + tid];
        sLr[tid] = g_lab[rowBase + tid];
        sLc[tid] = g_lab[colBase + tid];
    }

    const uint32_t sbase = smem_u32(smem);
    const int l7 = lid & 7;
    uint32_t aRow[2];
#pragma unroll
    for (int mf = 0; mf < 2; mf++)
        aRow[mf] = (uint32_t)((warpM * 32 + mf * 16 + ((lid >> 3) & 1) * 8 + l7) * 128);
    const int aSel = lid >> 4;
    uint32_t bCol[4];
#pragma unroll
    for (int p = 0; p < 4; p++)
        bCol[p] = (uint32_t)((warpN * 64 + p * 16 + (lid >> 4) * 8 + l7) * 128);
    const int bSel = (lid >> 3) & 1;

    // chunk loader: 128 rows x 128B (= 64 fp16), SW128 swizzle
    auto load_chunk = [&](const __half* __restrict__ base, int rb, int kt, uint32_t dst) {
#pragma unroll
        for (int i = 0; i < 4; i++) {
            int f = tid + i * 256;
            int r = f >> 3;
            int c16 = f & 7;
            const __half* g = base + (size_t)(rb + r) * DD + kt + c16 * 8;
            cp_async16(dst + r * 128 + ((c16 ^ (r & 7)) << 4), g);
        }
    };

    float acc[2][8][4];
#pragma unroll
    for (int mf = 0; mf < 2; mf++)
#pragma unroll
        for (int nf = 0; nf < 8; nf++)
#pragma unroll
            for (int v = 0; v < 4; v++) acc[mf][nf][v] = 0.f;

    // prologue: chunks 0,1 in flight
    load_chunk(g_srch, rowBase, 0, sbase + A_OFF(0));
    load_chunk(g_tgth, colBase, 0, sbase + B_OFF(0));
    asm volatile("cp.async.commit_group;");
    load_chunk(g_srch, rowBase, KC, sbase + A_OFF(1));
    load_chunk(g_tgth, colBase, KC, sbase + B_OFF(1));
    asm volatile("cp.async.commit_group;");

    for (int c = 0; c < NCHUNK; c++) {
        // ensure chunk c's fills landed (chunk c+1 may stay in flight)
        if (c + 1 < NCHUNK) asm volatile("cp.async.wait_group 1;");
        else                asm volatile("cp.async.wait_group 0;");
        // single barrier: (1) publish chunk c fills to all threads,
        // (2) all warps finished computing chunk c-1 -> its stage is reusable
        __syncthreads();
        if (c + 2 < NCHUNK) {
            int sn = (c + 2) % NSTAGE;   // == (c-1)%NSTAGE, consumed at c-1
            load_chunk(g_srch, rowBase, (c + 2) * KC, sbase + A_OFF(sn));
            load_chunk(g_tgth, colBase, (c + 2) * KC, sbase + B_OFF(sn));
            asm volatile("cp.async.commit_group;");
        }

        const uint32_t Ab = sbase + A_OFF(c % NSTAGE);
        const uint32_t Bb = sbase + B_OFF(c % NSTAGE);
#pragma unroll
        for (int s = 0; s < 4; s++) {          // 4 x K=16
            uint32_t a[2][4];
#pragma unroll
            for (int mf = 0; mf < 2; mf++) {
                uint32_t addr = Ab + aRow[mf] + ((uint32_t)((s * 2 + aSel) ^ l7) << 4);
                ldsm_x4(addr, a[mf][0], a[mf][1], a[mf][2], a[mf][3]);
            }
#pragma unroll
            for (int p = 0; p < 4; p++) {
                uint32_t b0a, b1a, b0b, b1b;
                uint32_t addr = Bb + bCol[p] + ((uint32_t)((s * 2 + bSel) ^ l7) << 4);
                ldsm_x4(addr, b0a, b1a, b0b, b1b);
                mma_f16(acc[0][2 * p],     a[0][0], a[0][1], a[0][2], a[0][3], b0a, b1a);
                mma_f16(acc[1][2 * p],     a[1][0], a[1][1], a[1][2], a[1][3], b0a, b1a);
                mma_f16(acc[0][2 * p + 1], a[0][0], a[0][1], a[0][2], a[0][3], b0b, b1b);
                mma_f16(acc[1][2 * p + 1], a[1][0], a[1][1], a[1][2], a[1][3], b0b, b1b);
            }
        }
    }
    __syncthreads();   // protect sAp/sAn init vs epilogue (and last stage)

    // ---- epilogue: dist -> clamp -> mask -> row max/min ----
#pragma unroll
    for (int mf = 0; mf < 2; mf++) {
#pragma unroll
        for (int half = 0; half < 2; half++) {
            int row = warpM * 32 + mf * 16 + half * 8 + gid;
            float e1v = sE1[row];
            int   lr  = sLr[row];
            float apv = 0.f;
            float anv = __int_as_float(0x7f800000);
#pragma unroll
            for (int nf = 0; nf < 8; nf++) {
                int c0 = warpN * 64 + nf * 8 + t4 * 2;
#pragma unroll
                for (int v = 0; v < 2; v++) {
                    int col = c0 + v;
                    float d = fmaf(-2.f, acc[mf][nf][half * 2 + v], e1v + sE2[col]);
                    d = fmaxf(d, 0.f);
                    if (lr == sLc[col]) apv = fmaxf(apv, d);
                    else                anv = fminf(anv, d);
                }
            }
#pragma unroll
            for (int o = 1; o <= 2; o <<= 1) {
                apv = fmaxf(apv, __shfl_xor_sync(0xffffffffu, apv, o));
                anv = fminf(anv, __shfl_xor_sync(0xffffffffu, anv, o));
            }
            if (t4 == 0) {
                atomicMax(&sAp[row], __float_as_uint(apv));
                atomicMin(&sAn[row], __float_as_uint(anv));
            }
        }
    }
    __syncthreads();
    if (tid < 128) {
        atomicMax(&g_ap[rowBase + tid], sAp[tid]);
        atomicMin(&g_an[rowBase + tid], sAn[tid]);
    }
}

// ---------------------------------------------------------------------------
// reduce: deterministic single-block mean of relu(ap - an + margin)
// ---------------------------------------------------------------------------
__global__ void reduce_kernel(float* __restrict__ out) {
    __shared__ float sw[32];
    int t = threadIdx.x;  // 1024
    float s = 0.f;
#pragma unroll
    for (int i = t; i < NN; i += 1024) {
        float ap = __uint_as_float(g_ap[i]);
        float an = __uint_as_float(g_an[i]);
        s += fmaxf(ap - an + MARGIN_F, 0.f);
    }
#pragma unroll
    for (int o = 16; o > 0; o >>= 1) s += __shfl_xor_sync(0xffffffffu, s, o);
    if ((t & 31) == 0) sw[t >> 5] = s;
    __syncthreads();
    if (t < 32) {
        float v = sw[t];
#pragma unroll
        for (int o = 16; o > 0; o >>= 1) v += __shfl_xor_sync(0xffffffffu, v, o);
        if (t == 0) out[0] = v * (1.0f / (float)NN);
    }
}

// ---------------------------------------------------------------------------
extern "C" void kernel_launch(void* const* d_in, const int* in_sizes, int n_in,
                              void* d_out, int out_size) {
    const float* src = (const float*)d_in[0];
    const float* tgt = (const float*)d_in[1];
    const int*   lab = (const int*)d_in[2];

    cudaFuncSetAttribute(dist_mma_kernel,
                         cudaFuncAttributeMaxDynamicSharedMemorySize, DYN_SMEM);

    prep_kernel<<<NN / 8, 256>>>(src, tgt, lab);
    dist_mma_kernel<<<dim3(NN / BN, NN / BM), 256, DYN_SMEM>>>();
    reduce_kernel<<<1, 1024>>>((float*)d_out);
}

// round 11
// speedup vs baseline: 1.2708x; 1.0381x over previous
#include <cuda_runtime.h>
#include <cuda_fp16.h>
#include <cstdint>

#define NN 4096
#define DD 512
#define BM 128
#define BN 128
#define KC 64                    // fp16 K elems per chunk = 128B per row
#define NCHUNK (DD / KC)         // 8
#define MARGIN_F 0.3f

#define TILE_BYTES (BM * 128)    // 16 KB per operand per stage
#define A_OFF(s) ((s) * TILE_BYTES)
#define B_OFF(s) (2 * TILE_BYTES + (s) * TILE_BYTES)
#define DYN_SMEM (4 * TILE_BYTES)   // 64 KB (2-stage double buffer)

__device__ float    g_e1[NN];
__device__ float    g_e2[NN];
__device__ unsigned g_ap[NN];      // non-negative float bits, atomicMax
__device__ unsigned g_an[NN];      // non-negative float bits, atomicMin
__device__ int      g_lab[NN];
__device__ __half   g_srch[NN * DD];   // fp16 copies (4 MB each)
__device__ __half   g_tgth[NN * DD];

// ---------------------------------------------------------------------------
__device__ __forceinline__ uint32_t h2_bits(__half2 h) {
    return *reinterpret_cast<uint32_t*>(&h);
}
__device__ __forceinline__ uint32_t smem_u32(const void* p) {
    uint32_t a;
    asm("{ .reg .u64 t; cvta.to.shared.u64 t, %1; cvt.u32.u64 %0, t; }"
        : "=r"(a) : "l"(p));
    return a;
}
__device__ __forceinline__ void cp_async16(uint32_t dst, const void* src) {
    asm volatile("cp.async.cg.shared.global [%0], [%1], 16;" :: "r"(dst), "l"(src));
}
__device__ __forceinline__ void ldsm_x4(uint32_t addr, uint32_t& r0, uint32_t& r1,
                                        uint32_t& r2, uint32_t& r3) {
    asm volatile("ldmatrix.sync.aligned.m8n8.x4.shared.b16 {%0,%1,%2,%3}, [%4];"
                 : "=r"(r0), "=r"(r1), "=r"(r2), "=r"(r3) : "r"(addr));
}
__device__ __forceinline__ void mma_f16(float* d, uint32_t a0, uint32_t a1,
                                        uint32_t a2, uint32_t a3,
                                        uint32_t b0, uint32_t b1) {
    asm volatile(
        "mma.sync.aligned.m16n8k16.row.col.f32.f16.f16.f32 "
        "{%0,%1,%2,%3}, {%4,%5,%6,%7}, {%8,%9}, {%0,%1,%2,%3};"
        : "+f"(d[0]), "+f"(d[1]), "+f"(d[2]), "+f"(d[3])
        : "r"(a0), "r"(a1), "r"(a2), "r"(a3), "r"(b0), "r"(b1));
}

// ---------------------------------------------------------------------------
// prep: warp-per-row fp32->fp16 convert + squared norms + accumulator init.
// 512 blocks x 256 threads. Block 0 additionally: label detect + normalize.
// ---------------------------------------------------------------------------
__global__ void __launch_bounds__(256) prep_kernel(const float* __restrict__ src,
                                                   const float* __restrict__ tgt,
                                                   const int* __restrict__ lab32) {
    const int wid = threadIdx.x >> 5;
    const int lid = threadIdx.x & 31;
    const int row = blockIdx.x * 8 + wid;

    const float4* s4 = (const float4*)(src + (size_t)row * DD);
    const float4* g4 = (const float4*)(tgt + (size_t)row * DD);
    uint2* sh = (uint2*)(g_srch + (size_t)row * DD);
    uint2* gh = (uint2*)(g_tgth + (size_t)row * DD);

    float4 xs[4], ys[4];
#pragma unroll
    for (int i = 0; i < 4; i++) xs[i] = s4[lid + 32 * i];
#pragma unroll
    for (int i = 0; i < 4; i++) ys[i] = g4[lid + 32 * i];

    float a = 0.f, b = 0.f;
#pragma unroll
    for (int i = 0; i < 4; i++) {
        float4 x = xs[i];
        a = fmaf(x.x, x.x, a); a = fmaf(x.y, x.y, a);
        a = fmaf(x.z, x.z, a); a = fmaf(x.w, x.w, a);
        uint2 o;
        o.x = h2_bits(__floats2half2_rn(x.x, x.y));
        o.y = h2_bits(__floats2half2_rn(x.z, x.w));
        sh[lid + 32 * i] = o;
        float4 y = ys[i];
        b = fmaf(y.x, y.x, b); b = fmaf(y.y, y.y, b);
        b = fmaf(y.z, y.z, b); b = fmaf(y.w, y.w, b);
        o.x = h2_bits(__floats2half2_rn(y.x, y.y));
        o.y = h2_bits(__floats2half2_rn(y.z, y.w));
        gh[lid + 32 * i] = o;
    }
#pragma unroll
    for (int o = 16; o > 0; o >>= 1) {
        a += __shfl_xor_sync(0xffffffffu, a, o);
        b += __shfl_xor_sync(0xffffffffu, b, o);
    }
    if (lid == 0) {
        g_e1[row] = a;
        g_e2[row] = b;
        g_ap[row] = 0u;
        g_an[row] = 0x7f800000u;
    }

    // ---- block 0 extra duty: labels (global dtype detection) ----
    if (blockIdx.x == 0) {
        __shared__ int any_odd_nonzero;
        const int t = threadIdx.x;
        if (t == 0) any_odd_nonzero = 0;
        __syncthreads();
        int local = 0;
        for (int i = 2 * t + 1; i < NN; i += 2 * 256)
            if (lab32[i] != 0) local = 1;
        if (local) atomicOr(&any_odd_nonzero, 1);
        __syncthreads();
        bool is64 = (any_odd_nonzero == 0);
        for (int i = t; i < NN; i += 256)
            g_lab[i] = is64 ? lab32[2 * i] : lab32[i];
    }
}

// ---------------------------------------------------------------------------
// dist_mma: EXACT R7 structure (best measured): 128x128 tile, fp16 m16n8k16,
// ldmatrix fragment feed, 2-stage cp.async double buffer with loads issued
// before the wait, fused label-masked row max/min epilogue.
// 8 warps: 4 (M) x 2 (N); warp tile 32x64.
// ---------------------------------------------------------------------------
__global__ void __launch_bounds__(256, 2) dist_mma_kernel() {
    extern __shared__ char smem[];
    __shared__ float sE1[BM], sE2[BN];
    __shared__ int   sLr[BM], sLc[BN];
    __shared__ unsigned sAp[BM], sAn[BM];

    const int tid = threadIdx.x;
    const int wid = tid >> 5;
    const int lid = tid & 31;
    const int gid = lid >> 2;
    const int t4  = lid & 3;
    const int warpM = wid & 3;
    const int warpN = wid >> 2;
    const int rowBase = blockIdx.y * BM;
    const int colBase = blockIdx.x * BN;

    if (tid < 128) {
        sAp[tid] = 0u;
        sAn[tid] = 0x7f800000u;
        sE1[tid] = g_e1[rowBase + tid];
        sE2[tid] = g_e2[colBase + tid];
        sLr[tid] = g_lab[rowBase + tid];
        sLc[tid] = g_lab[colBase + tid];
    }

    const uint32_t sbase = smem_u32(smem);
    const int l7 = lid & 7;
    uint32_t aRow[2];
#pragma unroll
    for (int mf = 0; mf < 2; mf++)
        aRow[mf] = (uint32_t)((warpM * 32 + mf * 16 + ((lid >> 3) & 1) * 8 + l7) * 128);
    const int aSel = lid >> 4;
    uint32_t bCol[4];
#pragma unroll
    for (int p = 0; p < 4; p++)
        bCol[p] = (uint32_t)((warpN * 64 + p * 16 + (lid >> 4) * 8 + l7) * 128);
    const int bSel = (lid >> 3) & 1;

    // chunk loader: 128 rows x 128B (= 64 fp16), SW128 swizzle
    auto load_chunk = [&](const __half* __restrict__ base, int rb, int kt, uint32_t dst) {
#pragma unroll
        for (int i = 0; i < 4; i++) {
            int f = tid + i * 256;
            int r = f >> 3;
            int c16 = f & 7;
            const __half* g = base + (size_t)(rb + r) * DD + kt + c16 * 8;
            cp_async16(dst + r * 128 + ((c16 ^ (r & 7)) << 4), g);
        }
    };

    float acc[2][8][4];
#pragma unroll
    for (int mf = 0; mf < 2; mf++)
#pragma unroll
        for (int nf = 0; nf < 8; nf++)
#pragma unroll
            for (int v = 0; v < 4; v++) acc[mf][nf][v] = 0.f;

    load_chunk(g_srch, rowBase, 0, sbase + A_OFF(0));
    load_chunk(g_tgth, colBase, 0, sbase + B_OFF(0));
    asm volatile("cp.async.commit_group;");

    for (int c = 0; c < NCHUNK; c++) {
        int st = c & 1;
        if (c + 1 < NCHUNK) {
            int sn = (c + 1) & 1;
            load_chunk(g_srch, rowBase, (c + 1) * KC, sbase + A_OFF(sn));
            load_chunk(g_tgth, colBase, (c + 1) * KC, sbase + B_OFF(sn));
            asm volatile("cp.async.commit_group;");
            asm volatile("cp.async.wait_group 1;");
        } else {
            asm volatile("cp.async.wait_group 0;");
        }
        __syncthreads();

        const uint32_t Ab = sbase + A_OFF(st);
        const uint32_t Bb = sbase + B_OFF(st);
#pragma unroll
        for (int s = 0; s < 4; s++) {          // 4 x K=16
            uint32_t a[2][4];
#pragma unroll
            for (int mf = 0; mf < 2; mf++) {
                uint32_t addr = Ab + aRow[mf] + ((uint32_t)((s * 2 + aSel) ^ l7) << 4);
                ldsm_x4(addr, a[mf][0], a[mf][1], a[mf][2], a[mf][3]);
            }
#pragma unroll
            for (int p = 0; p < 4; p++) {
                uint32_t b0a, b1a, b0b, b1b;
                uint32_t addr = Bb + bCol[p] + ((uint32_t)((s * 2 + bSel) ^ l7) << 4);
                ldsm_x4(addr, b0a, b1a, b0b, b1b);
                mma_f16(acc[0][2 * p],     a[0][0], a[0][1], a[0][2], a[0][3], b0a, b1a);
                mma_f16(acc[1][2 * p],     a[1][0], a[1][1], a[1][2], a[1][3], b0a, b1a);
                mma_f16(acc[0][2 * p + 1], a[0][0], a[0][1], a[0][2], a[0][3], b0b, b1b);
                mma_f16(acc[1][2 * p + 1], a[1][0], a[1][1], a[1][2], a[1][3], b0b, b1b);
            }
        }
        __syncthreads();
    }

    // ---- epilogue: dist -> clamp -> mask -> row max/min ----
#pragma unroll
    for (int mf = 0; mf < 2; mf++) {
#pragma unroll
        for (int half = 0; half < 2; half++) {
            int row = warpM * 32 + mf * 16 + half * 8 + gid;
            float e1v = sE1[row];
            int   lr  = sLr[row];
            float apv = 0.f;
            float anv = __int_as_float(0x7f800000);
#pragma unroll
            for (int nf = 0; nf < 8; nf++) {
                int c0 = warpN * 64 + nf * 8 + t4 * 2;
#pragma unroll
                for (int v = 0; v < 2; v++) {
                    int col = c0 + v;
                    float d = fmaf(-2.f, acc[mf][nf][half * 2 + v], e1v + sE2[col]);
                    d = fmaxf(d, 0.f);
                    if (lr == sLc[col]) apv = fmaxf(apv, d);
                    else                anv = fminf(anv, d);
                }
            }
#pragma unroll
            for (int o = 1; o <= 2; o <<= 1) {
                apv = fmaxf(apv, __shfl_xor_sync(0xffffffffu, apv, o));
                anv = fminf(anv, __shfl_xor_sync(0xffffffffu, anv, o));
            }
            if (t4 == 0) {
                atomicMax(&sAp[row], __float_as_uint(apv));
                atomicMin(&sAn[row], __float_as_uint(anv));
            }
        }
    }
    __syncthreads();
    if (tid < 128) {
        atomicMax(&g_ap[rowBase + tid], sAp[tid]);
        atomicMin(&g_an[rowBase + tid], sAn[tid]);
    }
}

// ---------------------------------------------------------------------------
// reduce: deterministic single-block mean of relu(ap - an + margin)
// ---------------------------------------------------------------------------
__global__ void reduce_kernel(float* __restrict__ out) {
    __shared__ float sw[32];
    int t = threadIdx.x;  // 1024
    float s = 0.f;
#pragma unroll
    for (int i = t; i < NN; i += 1024) {
        float ap = __uint_as_float(g_ap[i]);
        float an = __uint_as_float(g_an[i]);
        s += fmaxf(ap - an + MARGIN_F, 0.f);
    }
#pragma unroll
    for (int o = 16; o > 0; o >>= 1) s += __shfl_xor_sync(0xffffffffu, s, o);
    if ((t & 31) == 0) sw[t >> 5] = s;
    __syncthreads();
    if (t < 32) {
        float v = sw[t];
#pragma unroll
        for (int o = 16; o > 0; o >>= 1) v += __shfl_xor_sync(0xffffffffu, v, o);
        if (t == 0) out[0] = v * (1.0f / (float)NN);
    }
}

// ---------------------------------------------------------------------------
extern "C" void kernel_launch(void* const* d_in, const int* in_sizes, int n_in,
                              void* d_out, int out_size) {
    const float* src = (const float*)d_in[0];
    const float* tgt = (const float*)d_in[1];
    const int*   lab = (const int*)d_in[2];

    cudaFuncSetAttribute(dist_mma_kernel,
                         cudaFuncAttributeMaxDynamicSharedMemorySize, DYN_SMEM);

    prep_kernel<<<NN / 8, 256>>>(src, tgt, lab);
    dist_mma_kernel<<<dim3(NN / BN, NN / BM), 256, DYN_SMEM>>>();
    reduce_kernel<<<1, 1024>>>((float*)d_out);
}

// round 12
// speedup vs baseline: 1.2716x; 1.0006x over previous
#include <cuda_runtime.h>
#include <cuda_fp16.h>
#include <cstdint>

#define NN 4096
#define DD 512
#define BM 128
#define BN 128
#define KC 64                    // fp16 K elems per chunk = 128B per row
#define NCHUNK (DD / KC)         // 8
#define MARGIN_F 0.3f

#define TILE_BYTES (BM * 128)    // 16 KB per operand per stage
#define A_OFF(s) ((s) * TILE_BYTES)
#define B_OFF(s) (2 * TILE_BYTES + (s) * TILE_BYTES)
#define DYN_SMEM (4 * TILE_BYTES)   // 64 KB (2-stage double buffer)

__device__ float    g_e1[NN];
__device__ float    g_e2[NN];
__device__ unsigned g_ap[NN];      // non-negative float bits, atomicMax
__device__ unsigned g_an[NN];      // non-negative float bits, atomicMin
__device__ int      g_lab[NN];
__device__ __half   g_srch[NN * DD];   // fp16 copies (4 MB each)
__device__ __half   g_tgth[NN * DD];

// ---------------------------------------------------------------------------
__device__ __forceinline__ uint32_t h2_bits(__half2 h) {
    return *reinterpret_cast<uint32_t*>(&h);
}
__device__ __forceinline__ uint32_t smem_u32(const void* p) {
    uint32_t a;
    asm("{ .reg .u64 t; cvta.to.shared.u64 t, %1; cvt.u32.u64 %0, t; }"
        : "=r"(a) : "l"(p));
    return a;
}
__device__ __forceinline__ void cp_async16(uint32_t dst, const void* src) {
    asm volatile("cp.async.cg.shared.global [%0], [%1], 16;" :: "r"(dst), "l"(src));
}
__device__ __forceinline__ void ldsm_x4(uint32_t addr, uint32_t& r0, uint32_t& r1,
                                        uint32_t& r2, uint32_t& r3) {
    asm volatile("ldmatrix.sync.aligned.m8n8.x4.shared.b16 {%0,%1,%2,%3}, [%4];"
                 : "=r"(r0), "=r"(r1), "=r"(r2), "=r"(r3) : "r"(addr));
}
__device__ __forceinline__ void mma_f16(float* d, uint32_t a0, uint32_t a1,
                                        uint32_t a2, uint32_t a3,
                                        uint32_t b0, uint32_t b1) {
    asm volatile(
        "mma.sync.aligned.m16n8k16.row.col.f32.f16.f16.f32 "
        "{%0,%1,%2,%3}, {%4,%5,%6,%7}, {%8,%9}, {%0,%1,%2,%3};"
        : "+f"(d[0]), "+f"(d[1]), "+f"(d[2]), "+f"(d[3])
        : "r"(a0), "r"(a1), "r"(a2), "r"(a3), "r"(b0), "r"(b1));
}

// ---------------------------------------------------------------------------
// prep: warp-per-(row, array). 1024 blocks x 256 threads = 8192 warps:
// warp slot s -> row = s>>1, array = s&1 (0=src, 1=tgt).
// Each lane: 4 independent LDG.128 + 4 STG.64; warp-shuffle norm reduction.
// Block 0 additionally: label dtype detect + normalize.
// ---------------------------------------------------------------------------
__global__ void __launch_bounds__(256) prep_kernel(const float* __restrict__ src,
                                                   const float* __restrict__ tgt,
                                                   const int* __restrict__ lab32) {
    const int wid = threadIdx.x >> 5;
    const int lid = threadIdx.x & 31;
    const int slot = blockIdx.x * 8 + wid;
    const int row = slot >> 1;
    const int arr = slot & 1;

    const float* base = arr ? tgt : src;
    __half* dsth = arr ? g_tgth : g_srch;

    const float4* s4 = (const float4*)(base + (size_t)row * DD);
    uint2* oh = (uint2*)(dsth + (size_t)row * DD);

    float4 xs[4];
#pragma unroll
    for (int i = 0; i < 4; i++) xs[i] = s4[lid + 32 * i];

    float a = 0.f;
#pragma unroll
    for (int i = 0; i < 4; i++) {
        float4 x = xs[i];
        a = fmaf(x.x, x.x, a); a = fmaf(x.y, x.y, a);
        a = fmaf(x.z, x.z, a); a = fmaf(x.w, x.w, a);
        uint2 o;
        o.x = h2_bits(__floats2half2_rn(x.x, x.y));
        o.y = h2_bits(__floats2half2_rn(x.z, x.w));
        oh[lid + 32 * i] = o;
    }
#pragma unroll
    for (int o = 16; o > 0; o >>= 1)
        a += __shfl_xor_sync(0xffffffffu, a, o);
    if (lid == 0) {
        if (arr == 0) {
            g_e1[row] = a;
            g_ap[row] = 0u;
            g_an[row] = 0x7f800000u;
        } else {
            g_e2[row] = a;
        }
    }

    // ---- block 0 extra duty: labels (global dtype detection) ----
    if (blockIdx.x == 0) {
        __shared__ int any_odd_nonzero;
        const int t = threadIdx.x;
        if (t == 0) any_odd_nonzero = 0;
        __syncthreads();
        int local = 0;
        for (int i = 2 * t + 1; i < NN; i += 2 * 256)
            if (lab32[i] != 0) local = 1;
        if (local) atomicOr(&any_odd_nonzero, 1);
        __syncthreads();
        bool is64 = (any_odd_nonzero == 0);
        for (int i = t; i < NN; i += 256)
            g_lab[i] = is64 ? lab32[2 * i] : lab32[i];
    }
}

// ---------------------------------------------------------------------------
// dist_mma: UNCHANGED from best measured (R7/R11): 128x128 tile, fp16
// m16n8k16, ldmatrix fragment feed, 2-stage cp.async double buffer with
// loads issued before the wait, fused label-masked row max/min epilogue.
// 8 warps: 4 (M) x 2 (N); warp tile 32x64.
// ---------------------------------------------------------------------------
__global__ void __launch_bounds__(256, 2) dist_mma_kernel() {
    extern __shared__ char smem[];
    __shared__ float sE1[BM], sE2[BN];
    __shared__ int   sLr[BM], sLc[BN];
    __shared__ unsigned sAp[BM], sAn[BM];

    const int tid = threadIdx.x;
    const int wid = tid >> 5;
    const int lid = tid & 31;
    const int gid = lid >> 2;
    const int t4  = lid & 3;
    const int warpM = wid & 3;
    const int warpN = wid >> 2;
    const int rowBase = blockIdx.y * BM;
    const int colBase = blockIdx.x * BN;

    if (tid < 128) {
        sAp[tid] = 0u;
        sAn[tid] = 0x7f800000u;
        sE1[tid] = g_e1[rowBase + tid];
        sE2[tid] = g_e2[colBase + tid];
        sLr[tid] = g_lab[rowBase + tid];
        sLc[tid] = g_lab[colBase + tid];
    }

    const uint32_t sbase = smem_u32(smem);
    const int l7 = lid & 7;
    uint32_t aRow[2];
#pragma unroll
    for (int mf = 0; mf < 2; mf++)
        aRow[mf] = (uint32_t)((warpM * 32 + mf * 16 + ((lid >> 3) & 1) * 8 + l7) * 128);
    const int aSel = lid >> 4;
    uint32_t bCol[4];
#pragma unroll
    for (int p = 0; p < 4; p++)
        bCol[p] = (uint32_t)((warpN * 64 + p * 16 + (lid >> 4) * 8 + l7) * 128);
    const int bSel = (lid >> 3) & 1;

    // chunk loader: 128 rows x 128B (= 64 fp16), SW128 swizzle
    auto load_chunk = [&](const __half* __restrict__ base, int rb, int kt, uint32_t dst) {
#pragma unroll
        for (int i = 0; i < 4; i++) {
            int f = tid + i * 256;
            int r = f >> 3;
            int c16 = f & 7;
            const __half* g = base + (size_t)(rb + r) * DD + kt + c16 * 8;
            cp_async16(dst + r * 128 + ((c16 ^ (r & 7)) << 4), g);
        }
    };

    float acc[2][8][4];
#pragma unroll
    for (int mf = 0; mf < 2; mf++)
#pragma unroll
        for (int nf = 0; nf < 8; nf++)
#pragma unroll
            for (int v = 0; v < 4; v++) acc[mf][nf][v] = 0.f;

    load_chunk(g_srch, rowBase, 0, sbase + A_OFF(0));
    load_chunk(g_tgth, colBase, 0, sbase + B_OFF(0));
    asm volatile("cp.async.commit_group;");

    for (int c = 0; c < NCHUNK; c++) {
        int st = c & 1;
        if (c + 1 < NCHUNK) {
            int sn = (c + 1) & 1;
            load_chunk(g_srch, rowBase, (c + 1) * KC, sbase + A_OFF(sn));
            load_chunk(g_tgth, colBase, (c + 1) * KC, sbase + B_OFF(sn));
            asm volatile("cp.async.commit_group;");
            asm volatile("cp.async.wait_group 1;");
        } else {
            asm volatile("cp.async.wait_group 0;");
        }
        __syncthreads();

        const uint32_t Ab = sbase + A_OFF(st);
        const uint32_t Bb = sbase + B_OFF(st);
#pragma unroll
        for (int s = 0; s < 4; s++) {          // 4 x K=16
            uint32_t a[2][4];
#pragma unroll
            for (int mf = 0; mf < 2; mf++) {
                uint32_t addr = Ab + aRow[mf] + ((uint32_t)((s * 2 + aSel) ^ l7) << 4);
                ldsm_x4(addr, a[mf][0], a[mf][1], a[mf][2], a[mf][3]);
            }
#pragma unroll
            for (int p = 0; p < 4; p++) {
                uint32_t b0a, b1a, b0b, b1b;
                uint32_t addr = Bb + bCol[p] + ((uint32_t)((s * 2 + bSel) ^ l7) << 4);
                ldsm_x4(addr, b0a, b1a, b0b, b1b);
                mma_f16(acc[0][2 * p],     a[0][0], a[0][1], a[0][2], a[0][3], b0a, b1a);
                mma_f16(acc[1][2 * p],     a[1][0], a[1][1], a[1][2], a[1][3], b0a, b1a);
                mma_f16(acc[0][2 * p + 1], a[0][0], a[0][1], a[0][2], a[0][3], b0b, b1b);
                mma_f16(acc[1][2 * p + 1], a[1][0], a[1][1], a[1][2], a[1][3], b0b, b1b);
            }
        }
        __syncthreads();
    }

    // ---- epilogue: dist -> clamp -> mask -> row max/min ----
#pragma unroll
    for (int mf = 0; mf < 2; mf++) {
#pragma unroll
        for (int half = 0; half < 2; half++) {
            int row = warpM * 32 + mf * 16 + half * 8 + gid;
            float e1v = sE1[row];
            int   lr  = sLr[row];
            float apv = 0.f;
            float anv = __int_as_float(0x7f800000);
#pragma unroll
            for (int nf = 0; nf < 8; nf++) {
                int c0 = warpN * 64 + nf * 8 + t4 * 2;
#pragma unroll
                for (int v = 0; v < 2; v++) {
                    int col = c0 + v;
                    float d = fmaf(-2.f, acc[mf][nf][half * 2 + v], e1v + sE2[col]);
                    d = fmaxf(d, 0.f);
                    if (lr == sLc[col]) apv = fmaxf(apv, d);
                    else                anv = fminf(anv, d);
                }
            }
#pragma unroll
            for (int o = 1; o <= 2; o <<= 1) {
                apv = fmaxf(apv, __shfl_xor_sync(0xffffffffu, apv, o));
                anv = fminf(anv, __shfl_xor_sync(0xffffffffu, anv, o));
            }
            if (t4 == 0) {
                atomicMax(&sAp[row], __float_as_uint(apv));
                atomicMin(&sAn[row], __float_as_uint(anv));
            }
        }
    }
    __syncthreads();
    if (tid < 128) {
        atomicMax(&g_ap[rowBase + tid], sAp[tid]);
        atomicMin(&g_an[rowBase + tid], sAn[tid]);
    }
}

// ---------------------------------------------------------------------------
// reduce: deterministic single-block mean; one uint4 load round (MLP=2/thread)
// ---------------------------------------------------------------------------
__global__ void reduce_kernel(float* __restrict__ out) {
    __shared__ float sw[32];
    int t = threadIdx.x;  // 1024; thread t owns rows 4t..4t+3
    uint4 ap4 = *(const uint4*)&g_ap[t * 4];
    uint4 an4 = *(const uint4*)&g_an[t * 4];
    float s = fmaxf(__uint_as_float(ap4.x) - __uint_as_float(an4.x) + MARGIN_F, 0.f)
            + fmaxf(__uint_as_float(ap4.y) - __uint_as_float(an4.y) + MARGIN_F, 0.f)
            + fmaxf(__uint_as_float(ap4.z) - __uint_as_float(an4.z) + MARGIN_F, 0.f)
            + fmaxf(__uint_as_float(ap4.w) - __uint_as_float(an4.w) + MARGIN_F, 0.f);
#pragma unroll
    for (int o = 16; o > 0; o >>= 1) s += __shfl_xor_sync(0xffffffffu, s, o);
    if ((t & 31) == 0) sw[t >> 5] = s;
    __syncthreads();
    if (t < 32) {
        float v = sw[t];
#pragma unroll
        for (int o = 16; o > 0; o >>= 1) v += __shfl_xor_sync(0xffffffffu, v, o);
        if (t == 0) out[0] = v * (1.0f / (float)NN);
    }
}

// ---------------------------------------------------------------------------
extern "C" void kernel_launch(void* const* d_in, const int* in_sizes, int n_in,
                              void* d_out, int out_size) {
    const float* src = (const float*)d_in[0];
    const float* tgt = (const float*)d_in[1];
    const int*   lab = (const int*)d_in[2];

    cudaFuncSetAttribute(dist_mma_kernel,
                         cudaFuncAttributeMaxDynamicSharedMemorySize, DYN_SMEM);

    prep_kernel<<<NN / 4, 256>>>(src, tgt, lab);
    dist_mma_kernel<<<dim3(NN / BN, NN / BM), 256, DYN_SMEM>>>();
    reduce_kernel<<<1, 1024>>>((float*)d_out);
}